// round 1
// baseline (speedup 1.0000x reference)
#include <cuda_runtime.h>

#define NN 100000
#define NE 1600000
#define CIN 128

// ---------------- scratch (device globals; no runtime allocation) ----------
static __device__ int   g_deg[NN];
static __device__ float g_dis[NN];
static __device__ float g_h[(size_t)NN * 128];   // dense-transform output
static __device__ float g_a[(size_t)NN * 128];   // aggregation buffer

// ---------------- degree / normalization ----------------------------------
__global__ void k_deg_init() {
    int i = blockIdx.x * blockDim.x + threadIdx.x;
    if (i < NN) g_deg[i] = 1;                       // self loop
}
__global__ void k_deg_count(const int* __restrict__ dst) {
    int e = blockIdx.x * blockDim.x + threadIdx.x;
    if (e < NE) atomicAdd(&g_deg[dst[e]], 1);
}
__global__ void k_dis() {
    int i = blockIdx.x * blockDim.x + threadIdx.x;
    if (i < NN) g_dis[i] = rsqrtf((float)g_deg[i]);
}

// ---------------- fused GEMM -----------------------------------------------
// h = f(in) @ W  where f = identity (layer 1) or relu(in + bin) (layers 2,3)
// agg = h * dis^2   (self-loop contribution, initializes the accumulator)
template <int COUT, bool RELU_IN>
__global__ void k_gemm(const float* __restrict__ in, const float* __restrict__ W,
                       const float* __restrict__ bin,
                       float* __restrict__ h, float* __restrict__ agg)
{
    constexpr int XP = 132;          // padded x pitch (kills LDS bank conflicts)
    constexpr int TN = COUT / 16;    // 8 (COUT=128) or 4 (COUT=64)
    extern __shared__ float sm[];
    float* Xs = sm;                  // 64 * XP
    float* Ws = sm + 64 * XP;        // 128 * COUT

    int tid  = threadIdx.x;
    int row0 = blockIdx.x * 64;

    for (int i = tid; i < CIN * COUT; i += 256) Ws[i] = W[i];
    for (int i = tid; i < 64 * CIN; i += 256) {
        int r = i >> 7, k = i & 127;
        int gr = row0 + r;
        float v = (gr < NN) ? in[gr * CIN + k] : 0.f;
        if (RELU_IN) v = fmaxf(v + bin[k], 0.f);
        Xs[r * XP + k] = v;
    }
    __syncthreads();

    int tx = tid & 15, ty = tid >> 4;
    float acc[4][TN];
#pragma unroll
    for (int i = 0; i < 4; i++)
#pragma unroll
        for (int j = 0; j < TN; j++) acc[i][j] = 0.f;

#pragma unroll 4
    for (int k = 0; k < CIN; k++) {
        float xv[4];
#pragma unroll
        for (int i = 0; i < 4; i++) xv[i] = Xs[(ty * 4 + i) * XP + k];
        float wv[TN];
        const float4* wp = reinterpret_cast<const float4*>(&Ws[k * COUT + tx * TN]);
#pragma unroll
        for (int j4 = 0; j4 < TN / 4; j4++) {
            float4 w4 = wp[j4];
            wv[j4 * 4 + 0] = w4.x; wv[j4 * 4 + 1] = w4.y;
            wv[j4 * 4 + 2] = w4.z; wv[j4 * 4 + 3] = w4.w;
        }
#pragma unroll
        for (int i = 0; i < 4; i++)
#pragma unroll
            for (int j = 0; j < TN; j++) acc[i][j] += xv[i] * wv[j];
    }

#pragma unroll
    for (int i = 0; i < 4; i++) {
        int gr = row0 + ty * 4 + i;
        if (gr < NN) {
            float ds = g_dis[gr];
            float d2 = ds * ds;
            float* hp = &h[gr * COUT + tx * TN];
            float* ap = &agg[gr * COUT + tx * TN];
#pragma unroll
            for (int j4 = 0; j4 < TN / 4; j4++) {
                float4 hv = make_float4(acc[i][j4*4+0], acc[i][j4*4+1],
                                        acc[i][j4*4+2], acc[i][j4*4+3]);
                float4 av = make_float4(hv.x * d2, hv.y * d2, hv.z * d2, hv.w * d2);
                reinterpret_cast<float4*>(hp)[j4] = hv;
                reinterpret_cast<float4*>(ap)[j4] = av;
            }
        }
    }
}

// ---------------- edge scatter: agg[dst] += h[src] * norm ------------------
template <int COUT>
__global__ void k_scatter(const int* __restrict__ src, const int* __restrict__ dst,
                          const float* __restrict__ h, float* __restrict__ agg)
{
    constexpr int CH = COUT / 4;                 // float4 chunks per edge
    constexpr int SH = (COUT == 128) ? 5 : 4;
    unsigned idx = blockIdx.x * blockDim.x + threadIdx.x;
    if (idx >= (unsigned)NE * CH) return;
    int e = (int)(idx >> SH);
    int c = (int)(idx & (CH - 1));
    int s = src[e], d = dst[e];
    float nrm = g_dis[s] * g_dis[d];
    float4 v = *reinterpret_cast<const float4*>(&h[s * COUT + c * 4]);
    float* p = &agg[d * COUT + c * 4];
    asm volatile("red.global.add.v4.f32 [%0], {%1,%2,%3,%4};"
                 :: "l"(p), "f"(v.x * nrm), "f"(v.y * nrm),
                    "f"(v.z * nrm), "f"(v.w * nrm)
                 : "memory");
}

// ---------------- final epilogue: out = agg3 + b3 --------------------------
__global__ void k_final(const float* __restrict__ a3, const float* __restrict__ b3,
                        float* __restrict__ out)
{
    int i = blockIdx.x * blockDim.x + threadIdx.x;
    if (i < NN * 64) out[i] = a3[i] + b3[i & 63];
}

// ---------------- launcher --------------------------------------------------
extern "C" void kernel_launch(void* const* d_in, const int* in_sizes, int n_in,
                              void* d_out, int out_size)
{
    const float* x  = (const float*)d_in[0];
    const int*   ei = (const int*)d_in[1];
    const float* W1 = (const float*)d_in[2];
    const float* b1 = (const float*)d_in[3];
    const float* W2 = (const float*)d_in[4];
    const float* b2 = (const float*)d_in[5];
    const float* W3 = (const float*)d_in[6];
    const float* b3 = (const float*)d_in[7];
    float* out = (float*)d_out;

    const int* src = ei;            // edge_index[0]
    const int* dst = ei + NE;       // edge_index[1]

    float *ph = nullptr, *pa = nullptr;
    cudaGetSymbolAddress((void**)&ph, g_h);
    cudaGetSymbolAddress((void**)&pa, g_a);
    float* pa3 = ph + (size_t)NN * 64;   // layer-3 agg lives in upper half of g_h

    const int smem128 = (64 * 132 + 128 * 128) * 4;
    const int smem64  = (64 * 132 + 128 * 64) * 4;
    cudaFuncSetAttribute(k_gemm<128, false>, cudaFuncAttributeMaxDynamicSharedMemorySize, smem128);
    cudaFuncSetAttribute(k_gemm<128, true>,  cudaFuncAttributeMaxDynamicSharedMemorySize, smem128);
    cudaFuncSetAttribute(k_gemm<64,  true>,  cudaFuncAttributeMaxDynamicSharedMemorySize, smem64);

    // normalization
    k_deg_init<<<(NN + 255) / 256, 256>>>();
    k_deg_count<<<(NE + 255) / 256, 256>>>(dst);
    k_dis<<<(NN + 255) / 256, 256>>>();

    const int gB = (NN + 63) / 64;

    // layer 1: h1 = x@W1 ; agg1 = scatter(h1)
    k_gemm<128, false><<<gB, 256, smem128>>>(x, W1, nullptr, ph, pa);
    k_scatter<128><<<(NE * 32 + 255) / 256, 256>>>(src, dst, ph, pa);

    // layer 2: input = relu(agg1 + b1); in-place agg update is safe
    // (each block stages its own 64 input rows in smem before writing them)
    k_gemm<128, true><<<gB, 256, smem128>>>(pa, W2, b1, ph, pa);
    k_scatter<128><<<(NE * 32 + 255) / 256, 256>>>(src, dst, ph, pa);

    // layer 3 (COUT=64): input = relu(agg2 + b2); outputs go to g_h halves
    // (disjoint from input buffer pa -> no cross-block aliasing)
    k_gemm<64, true><<<gB, 256, smem64>>>(pa, W3, b2, ph, pa3);
    k_scatter<64><<<(NE * 16 + 255) / 256, 256>>>(src, dst, ph, pa3);

    k_final<<<(NN * 64 + 255) / 256, 256>>>(pa3, b3, out);
}

// round 2
// speedup vs baseline: 1.9146x; 1.9146x over previous
#include <cuda_runtime.h>

#define NN 100000
#define NE 1600000
#define CIN 128
#define NBLK ((NN + 255) / 256)   // 391 scan blocks

// ---------------- scratch ---------------------------------------------------
static __device__ int   g_deg[NN];
static __device__ int   g_cur[NN];
static __device__ float g_dis[NN];
static __device__ int   g_off[NN + 1];
static __device__ int   g_bsum[512];
static __device__ int   g_bscan[512];
static __device__ int2  g_ep[NE];                 // {src, dis[src] bits}
static __device__ float g_h[(size_t)NN * 128];    // dense-transform output
static __device__ float g_a[(size_t)NN * 128];    // aggregation buffer

// ---------------- degree / normalization ------------------------------------
__global__ void k_deg_init() {
    int i = blockIdx.x * blockDim.x + threadIdx.x;
    if (i < NN) { g_deg[i] = 1; g_cur[i] = 0; }   // self loop
}
__global__ void k_deg_count(const int* __restrict__ dst) {
    int e = blockIdx.x * blockDim.x + threadIdx.x;
    if (e < NE) atomicAdd(&g_deg[dst[e]], 1);
}
__global__ void k_dis() {
    int i = blockIdx.x * blockDim.x + threadIdx.x;
    if (i < NN) g_dis[i] = rsqrtf((float)g_deg[i]);
}

// ---------------- CSR build (offsets = scan of in-degree) -------------------
__global__ void k_scan1() {
    __shared__ int s[256];
    int t = threadIdx.x;
    int i = blockIdx.x * 256 + t;
    int v = (i < NN) ? (g_deg[i] - 1) : 0;
    s[t] = v; __syncthreads();
#pragma unroll
    for (int off = 1; off < 256; off <<= 1) {
        int a = (t >= off) ? s[t - off] : 0;
        __syncthreads();
        s[t] += a; __syncthreads();
    }
    if (i < NN) g_off[i] = s[t] - v;              // exclusive within block
    if (t == 255) g_bsum[blockIdx.x] = s[255];
}
__global__ void k_scan2() {
    __shared__ int s[512];
    int t = threadIdx.x;
    int v = (t < NBLK) ? g_bsum[t] : 0;
    s[t] = v; __syncthreads();
#pragma unroll
    for (int off = 1; off < 512; off <<= 1) {
        int a = (t >= off) ? s[t - off] : 0;
        __syncthreads();
        s[t] += a; __syncthreads();
    }
    g_bscan[t] = s[t] - v;
}
__global__ void k_scan3() {
    int i = blockIdx.x * blockDim.x + threadIdx.x;
    if (i < NN) g_off[i] += g_bscan[i >> 8];
    if (i == 0) g_off[NN] = NE;
}
__global__ void k_fill(const int* __restrict__ src, const int* __restrict__ dst) {
    int e = blockIdx.x * blockDim.x + threadIdx.x;
    if (e >= NE) return;
    int d = dst[e], s = src[e];
    int pos = g_off[d] + atomicAdd(&g_cur[d], 1);
    g_ep[pos] = make_int2(s, __float_as_int(g_dis[s]));
}

// ---------------- GEMM: h = f(in) @ W ---------------------------------------
// f = identity (layer 1) or relu(in + bin) (layers 2,3). 128x{128,64} block tile.
template <int COUT, bool RELU_IN>
__global__ void k_gemm(const float* __restrict__ in, const float* __restrict__ W,
                       const float* __restrict__ bin, float* __restrict__ h)
{
    constexpr int BM = 128, BK = 16;
    constexpr int XP = BM + 1;                       // 129
    constexpr int TM = (COUT == 128) ? 8 : 4;
    constexpr int NTX = COUT / 8;                    // 16 or 8
    __shared__ float Xs[BK * XP];
    __shared__ float Ws[BK * COUT];

    int tid = threadIdx.x;
    int row0 = blockIdx.x * BM;
    int tx = tid % NTX, ty = tid / NTX;

    float acc[TM][8];
#pragma unroll
    for (int i = 0; i < TM; i++)
#pragma unroll
        for (int j = 0; j < 8; j++) acc[i][j] = 0.f;

    for (int k0 = 0; k0 < CIN; k0 += BK) {
        // stage W chunk [BK x COUT], coalesced float4
        const float4* wg = reinterpret_cast<const float4*>(W + k0 * COUT);
        float4* ws4 = reinterpret_cast<float4*>(Ws);
#pragma unroll
        for (int i = tid; i < BK * COUT / 4; i += 256) ws4[i] = wg[i];

        // stage X chunk transposed: Xs[k][row]
#pragma unroll
        for (int idx = tid; idx < BM * 4; idx += 256) {
            int r = idx >> 2, q = idx & 3;
            int gr = row0 + r;
            float4 v = make_float4(0.f, 0.f, 0.f, 0.f);
            if (gr < NN)
                v = *reinterpret_cast<const float4*>(in + (size_t)gr * CIN + k0 + q * 4);
            if (RELU_IN) {
                float4 b = *reinterpret_cast<const float4*>(bin + k0 + q * 4);
                v.x = fmaxf(v.x + b.x, 0.f); v.y = fmaxf(v.y + b.y, 0.f);
                v.z = fmaxf(v.z + b.z, 0.f); v.w = fmaxf(v.w + b.w, 0.f);
            }
            Xs[(q * 4 + 0) * XP + r] = v.x;
            Xs[(q * 4 + 1) * XP + r] = v.y;
            Xs[(q * 4 + 2) * XP + r] = v.z;
            Xs[(q * 4 + 3) * XP + r] = v.w;
        }
        __syncthreads();

#pragma unroll
        for (int k = 0; k < BK; k++) {
            float xv[TM];
#pragma unroll
            for (int i = 0; i < TM; i++) xv[i] = Xs[k * XP + ty * TM + i];
            float4 w0 = *reinterpret_cast<float4*>(&Ws[k * COUT + tx * 8]);
            float4 w1 = *reinterpret_cast<float4*>(&Ws[k * COUT + tx * 8 + 4]);
            float wv[8] = {w0.x, w0.y, w0.z, w0.w, w1.x, w1.y, w1.z, w1.w};
#pragma unroll
            for (int i = 0; i < TM; i++)
#pragma unroll
                for (int j = 0; j < 8; j++) acc[i][j] = fmaf(xv[i], wv[j], acc[i][j]);
        }
        __syncthreads();
    }

#pragma unroll
    for (int i = 0; i < TM; i++) {
        int gr = row0 + ty * TM + i;
        if (gr < NN) {
            float4* hp = reinterpret_cast<float4*>(h + (size_t)gr * COUT + tx * 8);
            hp[0] = make_float4(acc[i][0], acc[i][1], acc[i][2], acc[i][3]);
            hp[1] = make_float4(acc[i][4], acc[i][5], acc[i][6], acc[i][7]);
        }
    }
}

// ---------------- gather: agg[d] = dis[d]*sum(dis[s]*h[s]) + dis[d]^2*h[d] --
__global__ void k_gather128(const float* __restrict__ h, float* __restrict__ agg)
{
    int warp = (blockIdx.x * blockDim.x + threadIdx.x) >> 5;
    int lane = threadIdx.x & 31;
    if (warp >= NN) return;
    int beg = g_off[warp], end = g_off[warp + 1];
    const float4* hp = reinterpret_cast<const float4*>(h);
    float4 acc = make_float4(0.f, 0.f, 0.f, 0.f);
    int i = beg;
    for (; i + 4 <= end; i += 4) {
        int2 e0 = g_ep[i], e1 = g_ep[i + 1], e2 = g_ep[i + 2], e3 = g_ep[i + 3];
        float4 v0 = hp[e0.x * 32 + lane];
        float4 v1 = hp[e1.x * 32 + lane];
        float4 v2 = hp[e2.x * 32 + lane];
        float4 v3 = hp[e3.x * 32 + lane];
        float w0 = __int_as_float(e0.y), w1 = __int_as_float(e1.y);
        float w2 = __int_as_float(e2.y), w3 = __int_as_float(e3.y);
        acc.x = fmaf(w0, v0.x, fmaf(w1, v1.x, fmaf(w2, v2.x, fmaf(w3, v3.x, acc.x))));
        acc.y = fmaf(w0, v0.y, fmaf(w1, v1.y, fmaf(w2, v2.y, fmaf(w3, v3.y, acc.y))));
        acc.z = fmaf(w0, v0.z, fmaf(w1, v1.z, fmaf(w2, v2.z, fmaf(w3, v3.z, acc.z))));
        acc.w = fmaf(w0, v0.w, fmaf(w1, v1.w, fmaf(w2, v2.w, fmaf(w3, v3.w, acc.w))));
    }
    for (; i < end; i++) {
        int2 e = g_ep[i];
        float4 v = hp[e.x * 32 + lane];
        float w = __int_as_float(e.y);
        acc.x = fmaf(w, v.x, acc.x); acc.y = fmaf(w, v.y, acc.y);
        acc.z = fmaf(w, v.z, acc.z); acc.w = fmaf(w, v.w, acc.w);
    }
    float dd = g_dis[warp], d2 = dd * dd;
    float4 hv = hp[warp * 32 + lane];
    acc.x = fmaf(acc.x, dd, d2 * hv.x);
    acc.y = fmaf(acc.y, dd, d2 * hv.y);
    acc.z = fmaf(acc.z, dd, d2 * hv.z);
    acc.w = fmaf(acc.w, dd, d2 * hv.w);
    reinterpret_cast<float4*>(agg)[warp * 32 + lane] = acc;
}

// final layer: COUT=64, fused +b3, writes straight to out
__global__ void k_gather64f(const float* __restrict__ h, const float* __restrict__ b3,
                            float* __restrict__ out)
{
    int warp = (blockIdx.x * blockDim.x + threadIdx.x) >> 5;
    int lane = threadIdx.x & 31;
    if (warp >= NN) return;
    int beg = g_off[warp], end = g_off[warp + 1];
    const float2* hp = reinterpret_cast<const float2*>(h);
    float2 acc = make_float2(0.f, 0.f);
    int i = beg;
    for (; i + 4 <= end; i += 4) {
        int2 e0 = g_ep[i], e1 = g_ep[i + 1], e2 = g_ep[i + 2], e3 = g_ep[i + 3];
        float2 v0 = hp[e0.x * 32 + lane];
        float2 v1 = hp[e1.x * 32 + lane];
        float2 v2 = hp[e2.x * 32 + lane];
        float2 v3 = hp[e3.x * 32 + lane];
        float w0 = __int_as_float(e0.y), w1 = __int_as_float(e1.y);
        float w2 = __int_as_float(e2.y), w3 = __int_as_float(e3.y);
        acc.x = fmaf(w0, v0.x, fmaf(w1, v1.x, fmaf(w2, v2.x, fmaf(w3, v3.x, acc.x))));
        acc.y = fmaf(w0, v0.y, fmaf(w1, v1.y, fmaf(w2, v2.y, fmaf(w3, v3.y, acc.y))));
    }
    for (; i < end; i++) {
        int2 e = g_ep[i];
        float2 v = hp[e.x * 32 + lane];
        float w = __int_as_float(e.y);
        acc.x = fmaf(w, v.x, acc.x); acc.y = fmaf(w, v.y, acc.y);
    }
    float dd = g_dis[warp], d2 = dd * dd;
    float2 hv = hp[warp * 32 + lane];
    float2 b = reinterpret_cast<const float2*>(b3)[lane];
    float2 r;
    r.x = fmaf(acc.x, dd, d2 * hv.x) + b.x;
    r.y = fmaf(acc.y, dd, d2 * hv.y) + b.y;
    reinterpret_cast<float2*>(out)[warp * 32 + lane] = r;
}

// ---------------- launcher ---------------------------------------------------
extern "C" void kernel_launch(void* const* d_in, const int* in_sizes, int n_in,
                              void* d_out, int out_size)
{
    const float* x  = (const float*)d_in[0];
    const int*   ei = (const int*)d_in[1];
    const float* W1 = (const float*)d_in[2];
    const float* b1 = (const float*)d_in[3];
    const float* W2 = (const float*)d_in[4];
    const float* b2 = (const float*)d_in[5];
    const float* W3 = (const float*)d_in[6];
    const float* b3 = (const float*)d_in[7];
    float* out = (float*)d_out;

    const int* src = ei;            // edge_index[0]
    const int* dst = ei + NE;       // edge_index[1]

    float *ph = nullptr, *pa = nullptr;
    cudaGetSymbolAddress((void**)&ph, g_h);
    cudaGetSymbolAddress((void**)&pa, g_a);

    // normalization + CSR build (amortized over 3 layers)
    k_deg_init<<<(NN + 255) / 256, 256>>>();
    k_deg_count<<<(NE + 255) / 256, 256>>>(dst);
    k_dis<<<(NN + 255) / 256, 256>>>();
    k_scan1<<<NBLK, 256>>>();
    k_scan2<<<1, 512>>>();
    k_scan3<<<NBLK, 256>>>();
    k_fill<<<(NE + 255) / 256, 256>>>(src, dst);

    const int gB = (NN + 127) / 128;
    const int gG = (NN * 32 + 255) / 256;   // warp per node

    // layer 1
    k_gemm<128, false><<<gB, 256>>>(x, W1, b1, ph);
    k_gather128<<<gG, 256>>>(ph, pa);
    // layer 2
    k_gemm<128, true><<<gB, 256>>>(pa, W2, b1, ph);
    k_gather128<<<gG, 256>>>(ph, pa);
    // layer 3 (COUT=64) + fused final bias
    k_gemm<64, true><<<gB, 256>>>(pa, W3, b2, ph);
    k_gather64f<<<gG, 256>>>(ph, b3, out);
}

// round 3
// speedup vs baseline: 2.0870x; 1.0900x over previous
#include <cuda_runtime.h>

#define NN 100000
#define NE 1600000
#define CIN 128
#define NBLK ((NN + 255) / 256)   // 391 scan blocks

// ---------------- scratch ---------------------------------------------------
static __device__ int   g_deg[NN];
static __device__ int   g_cur[NN];
static __device__ float g_dis[NN];
static __device__ int   g_off[NN + 1];
static __device__ int   g_bsum[512];
static __device__ int   g_bscan[512];
static __device__ int   g_ep[NE];                 // src per (dst-sorted) edge
static __device__ float g_h[(size_t)NN * 128];    // dis-scaled transform output
static __device__ float g_a[(size_t)NN * 128];    // aggregation buffer

// ---------------- f32x2 helpers ---------------------------------------------
__device__ __forceinline__ unsigned long long f2pack(float lo, float hi) {
    unsigned long long r;
    asm("mov.b64 %0, {%1, %2};" : "=l"(r) : "f"(lo), "f"(hi));
    return r;
}
__device__ __forceinline__ unsigned long long f2dup(float v) {
    unsigned long long r;
    asm("mov.b64 %0, {%1, %1};" : "=l"(r) : "f"(v));
    return r;
}
__device__ __forceinline__ void f2unpack(unsigned long long p, float& lo, float& hi) {
    asm("mov.b64 {%0, %1}, %2;" : "=f"(lo), "=f"(hi) : "l"(p));
}
#define FMA2(d, a, b, c) \
    asm("fma.rn.f32x2 %0, %1, %2, %3;" : "=l"(d) : "l"(a), "l"(b), "l"(c))

// ---------------- degree / normalization ------------------------------------
__global__ void k_deg_init() {
    int i = blockIdx.x * blockDim.x + threadIdx.x;
    if (i < NN) g_deg[i] = 1;                       // self loop
}
__global__ void k_deg_count(const int* __restrict__ dst) {
    int e = blockIdx.x * blockDim.x + threadIdx.x;
    if (e < NE) atomicAdd(&g_deg[dst[e]], 1);
}
__global__ void k_dis() {
    int i = blockIdx.x * blockDim.x + threadIdx.x;
    if (i < NN) g_dis[i] = rsqrtf((float)g_deg[i]);
}

// ---------------- CSR build (offsets = scan of in-degree) -------------------
__global__ void k_scan1() {
    __shared__ int s[256];
    int t = threadIdx.x;
    int i = blockIdx.x * 256 + t;
    int v = (i < NN) ? (g_deg[i] - 1) : 0;
    s[t] = v; __syncthreads();
#pragma unroll
    for (int off = 1; off < 256; off <<= 1) {
        int a = (t >= off) ? s[t - off] : 0;
        __syncthreads();
        s[t] += a; __syncthreads();
    }
    if (i < NN) g_off[i] = s[t] - v;              // exclusive within block
    if (t == 255) g_bsum[blockIdx.x] = s[255];
}
__global__ void k_scan2() {
    __shared__ int s[512];
    int t = threadIdx.x;
    int v = (t < NBLK) ? g_bsum[t] : 0;
    s[t] = v; __syncthreads();
#pragma unroll
    for (int off = 1; off < 512; off <<= 1) {
        int a = (t >= off) ? s[t - off] : 0;
        __syncthreads();
        s[t] += a; __syncthreads();
    }
    g_bscan[t] = s[t] - v;
}
__global__ void k_scan3() {
    int i = blockIdx.x * blockDim.x + threadIdx.x;
    if (i < NN) {
        int o = g_off[i] + g_bscan[i >> 8];
        g_off[i] = o;
        g_cur[i] = o;                              // seed fill cursor
    }
    if (i == 0) g_off[NN] = NE;
}
__global__ void k_fill(const int* __restrict__ src, const int* __restrict__ dst) {
    int e = blockIdx.x * blockDim.x + threadIdx.x;
    if (e >= NE) return;
    int pos = atomicAdd(&g_cur[dst[e]], 1);
    g_ep[pos] = src[e];
}

// ---------------- GEMM: h' = dis * (f(in) @ W) -------------------------------
// f = identity (layer 1) or relu(in + bin) (layers 2,3). f32x2 mainloop.
template <int COUT, bool RELU_IN>
__global__ void k_gemm(const float* __restrict__ in, const float* __restrict__ W,
                       const float* __restrict__ bin, float* __restrict__ h)
{
    constexpr int BM = 128, BK = 16;
    constexpr int XP = BM + 1;                       // 129
    constexpr int TM = (COUT == 128) ? 8 : 4;
    constexpr int NTX = COUT / 8;                    // 16 or 8
    __shared__ float Xs[BK * XP];
    __shared__ float Ws[BK * COUT];

    int tid = threadIdx.x;
    int row0 = blockIdx.x * BM;
    int tx = tid % NTX, ty = tid / NTX;

    unsigned long long acc[TM][4];
#pragma unroll
    for (int i = 0; i < TM; i++)
#pragma unroll
        for (int j = 0; j < 4; j++) acc[i][j] = 0ull;

    for (int k0 = 0; k0 < CIN; k0 += BK) {
        // stage W chunk [BK x COUT], coalesced float4
        const float4* wg = reinterpret_cast<const float4*>(W + k0 * COUT);
        float4* ws4 = reinterpret_cast<float4*>(Ws);
#pragma unroll
        for (int i = tid; i < BK * COUT / 4; i += 256) ws4[i] = wg[i];

        // stage X chunk transposed: Xs[k][row]
#pragma unroll
        for (int idx = tid; idx < BM * 4; idx += 256) {
            int r = idx >> 2, q = idx & 3;
            int gr = row0 + r;
            float4 v = make_float4(0.f, 0.f, 0.f, 0.f);
            if (gr < NN)
                v = *reinterpret_cast<const float4*>(in + (size_t)gr * CIN + k0 + q * 4);
            if (RELU_IN) {
                float4 b = *reinterpret_cast<const float4*>(bin + k0 + q * 4);
                v.x = fmaxf(v.x + b.x, 0.f); v.y = fmaxf(v.y + b.y, 0.f);
                v.z = fmaxf(v.z + b.z, 0.f); v.w = fmaxf(v.w + b.w, 0.f);
            }
            Xs[(q * 4 + 0) * XP + r] = v.x;
            Xs[(q * 4 + 1) * XP + r] = v.y;
            Xs[(q * 4 + 2) * XP + r] = v.z;
            Xs[(q * 4 + 3) * XP + r] = v.w;
        }
        __syncthreads();

#pragma unroll
        for (int k = 0; k < BK; k++) {
            unsigned long long xd[TM];
#pragma unroll
            for (int i = 0; i < TM; i++) xd[i] = f2dup(Xs[k * XP + ty * TM + i]);
            float4 w0 = *reinterpret_cast<float4*>(&Ws[k * COUT + tx * 8]);
            float4 w1 = *reinterpret_cast<float4*>(&Ws[k * COUT + tx * 8 + 4]);
            unsigned long long wp[4] = {
                f2pack(w0.x, w0.y), f2pack(w0.z, w0.w),
                f2pack(w1.x, w1.y), f2pack(w1.z, w1.w)
            };
#pragma unroll
            for (int i = 0; i < TM; i++)
#pragma unroll
                for (int j = 0; j < 4; j++) FMA2(acc[i][j], xd[i], wp[j], acc[i][j]);
        }
        __syncthreads();
    }

#pragma unroll
    for (int i = 0; i < TM; i++) {
        int gr = row0 + ty * TM + i;
        if (gr < NN) {
            float ds = g_dis[gr];
            float4 o0, o1;
            f2unpack(acc[i][0], o0.x, o0.y); f2unpack(acc[i][1], o0.z, o0.w);
            f2unpack(acc[i][2], o1.x, o1.y); f2unpack(acc[i][3], o1.z, o1.w);
            o0.x *= ds; o0.y *= ds; o0.z *= ds; o0.w *= ds;
            o1.x *= ds; o1.y *= ds; o1.z *= ds; o1.w *= ds;
            float4* hp = reinterpret_cast<float4*>(h + (size_t)gr * COUT + tx * 8);
            hp[0] = o0; hp[1] = o1;
        }
    }
}

// ---------------- gather: agg[d] = dis[d]*(sum_src h'[src] + h'[d]) ----------
__global__ void k_gather128(const float* __restrict__ h, float* __restrict__ agg)
{
    int warp = (blockIdx.x * blockDim.x + threadIdx.x) >> 5;
    int lane = threadIdx.x & 31;
    if (warp >= NN) return;
    int beg = g_off[warp], end = g_off[warp + 1];
    const float4* hp = reinterpret_cast<const float4*>(h);
    float4 acc = hp[warp * 32 + lane];                 // self term
    int i = beg;
    for (; i + 4 <= end; i += 4) {
        int s0 = g_ep[i], s1 = g_ep[i + 1], s2 = g_ep[i + 2], s3 = g_ep[i + 3];
        float4 v0 = hp[s0 * 32 + lane];
        float4 v1 = hp[s1 * 32 + lane];
        float4 v2 = hp[s2 * 32 + lane];
        float4 v3 = hp[s3 * 32 + lane];
        acc.x += (v0.x + v1.x) + (v2.x + v3.x);
        acc.y += (v0.y + v1.y) + (v2.y + v3.y);
        acc.z += (v0.z + v1.z) + (v2.z + v3.z);
        acc.w += (v0.w + v1.w) + (v2.w + v3.w);
    }
    for (; i < end; i++) {
        float4 v = hp[g_ep[i] * 32 + lane];
        acc.x += v.x; acc.y += v.y; acc.z += v.z; acc.w += v.w;
    }
    float dd = g_dis[warp];
    acc.x *= dd; acc.y *= dd; acc.z *= dd; acc.w *= dd;
    reinterpret_cast<float4*>(agg)[warp * 32 + lane] = acc;
}

// final layer: COUT=64, fused +b3, writes straight to out
__global__ void k_gather64f(const float* __restrict__ h, const float* __restrict__ b3,
                            float* __restrict__ out)
{
    int warp = (blockIdx.x * blockDim.x + threadIdx.x) >> 5;
    int lane = threadIdx.x & 31;
    if (warp >= NN) return;
    int beg = g_off[warp], end = g_off[warp + 1];
    const float2* hp = reinterpret_cast<const float2*>(h);
    float2 acc = hp[warp * 32 + lane];                 // self term
    int i = beg;
    for (; i + 4 <= end; i += 4) {
        int s0 = g_ep[i], s1 = g_ep[i + 1], s2 = g_ep[i + 2], s3 = g_ep[i + 3];
        float2 v0 = hp[s0 * 32 + lane];
        float2 v1 = hp[s1 * 32 + lane];
        float2 v2 = hp[s2 * 32 + lane];
        float2 v3 = hp[s3 * 32 + lane];
        acc.x += (v0.x + v1.x) + (v2.x + v3.x);
        acc.y += (v0.y + v1.y) + (v2.y + v3.y);
    }
    for (; i < end; i++) {
        float2 v = hp[g_ep[i] * 32 + lane];
        acc.x += v.x; acc.y += v.y;
    }
    float dd = g_dis[warp];
    float2 b = reinterpret_cast<const float2*>(b3)[lane];
    float2 r;
    r.x = fmaf(acc.x, dd, b.x);
    r.y = fmaf(acc.y, dd, b.y);
    reinterpret_cast<float2*>(out)[warp * 32 + lane] = r;
}

// ---------------- launcher ---------------------------------------------------
extern "C" void kernel_launch(void* const* d_in, const int* in_sizes, int n_in,
                              void* d_out, int out_size)
{
    const float* x  = (const float*)d_in[0];
    const int*   ei = (const int*)d_in[1];
    const float* W1 = (const float*)d_in[2];
    const float* b1 = (const float*)d_in[3];
    const float* W2 = (const float*)d_in[4];
    const float* b2 = (const float*)d_in[5];
    const float* W3 = (const float*)d_in[6];
    const float* b3 = (const float*)d_in[7];
    float* out = (float*)d_out;

    const int* src = ei;            // edge_index[0]
    const int* dst = ei + NE;       // edge_index[1]

    float *ph = nullptr, *pa = nullptr;
    cudaGetSymbolAddress((void**)&ph, g_h);
    cudaGetSymbolAddress((void**)&pa, g_a);

    // normalization + CSR build (amortized over 3 layers)
    k_deg_init<<<(NN + 255) / 256, 256>>>();
    k_deg_count<<<(NE + 255) / 256, 256>>>(dst);
    k_dis<<<(NN + 255) / 256, 256>>>();
    k_scan1<<<NBLK, 256>>>();
    k_scan2<<<1, 512>>>();
    k_scan3<<<NBLK, 256>>>();
    k_fill<<<(NE + 255) / 256, 256>>>(src, dst);

    const int gB = (NN + 127) / 128;
    const int gG = (NN * 32 + 255) / 256;   // warp per node

    // layer 1
    k_gemm<128, false><<<gB, 256>>>(x, W1, b1, ph);
    k_gather128<<<gG, 256>>>(ph, pa);
    // layer 2
    k_gemm<128, true><<<gB, 256>>>(pa, W2, b1, ph);
    k_gather128<<<gG, 256>>>(ph, pa);
    // layer 3 (COUT=64) + fused final bias
    k_gemm<64, true><<<gB, 256>>>(pa, W3, b2, ph);
    k_gather64f<<<gG, 256>>>(ph, b3, out);
}

// round 5
// speedup vs baseline: 2.8048x; 1.3440x over previous
#include <cuda_runtime.h>
#include <cuda_bf16.h>
#include <cstdint>

#define NN 100000
#define NE 1600000
#define CIN 128
#define NBLK ((NN + 255) / 256)   // 391 scan blocks

// ---------------- scratch ---------------------------------------------------
static __device__ int   g_deg[NN];
static __device__ int   g_cur[NN];
static __device__ float g_dis[NN];
static __device__ int   g_off[NN + 1];
static __device__ int   g_bsum[512];
static __device__ int   g_bscan[512];
static __device__ int   g_ep[NE];                 // src per (dst-sorted) edge
static __device__ float g_h[(size_t)NN * 128];    // dis-scaled transform output
static __device__ float g_a[(size_t)NN * 128];    // aggregation buffer
// pre-transposed + bf16 hi/lo split weights: [COUT][CIN] bf16
static __device__ __nv_bfloat16 g_w1h[128 * 128], g_w1l[128 * 128];
static __device__ __nv_bfloat16 g_w2h[128 * 128], g_w2l[128 * 128];
static __device__ __nv_bfloat16 g_w3h[64 * 128],  g_w3l[64 * 128];

// ---------------- PTX helpers ------------------------------------------------
__device__ __forceinline__ uint32_t smem_u32(const void* p) {
    uint32_t a;
    asm("{ .reg .u64 t; cvta.to.shared.u64 t, %1; cvt.u32.u64 %0, t; }" : "=r"(a) : "l"(p));
    return a;
}
__device__ __forceinline__ void ldsm4(uint32_t* r, uint32_t addr) {
    asm volatile("ldmatrix.sync.aligned.m8n8.x4.shared.b16 {%0,%1,%2,%3}, [%4];"
                 : "=r"(r[0]), "=r"(r[1]), "=r"(r[2]), "=r"(r[3]) : "r"(addr));
}
__device__ __forceinline__ void mma16816(float* d, const uint32_t* a,
                                         uint32_t b0, uint32_t b1) {
    asm volatile(
        "mma.sync.aligned.m16n8k16.row.col.f32.bf16.bf16.f32 "
        "{%0,%1,%2,%3}, {%4,%5,%6,%7}, {%8,%9}, {%0,%1,%2,%3};"
        : "+f"(d[0]), "+f"(d[1]), "+f"(d[2]), "+f"(d[3])
        : "r"(a[0]), "r"(a[1]), "r"(a[2]), "r"(a[3]), "r"(b0), "r"(b1));
}

// ---------------- degree / normalization ------------------------------------
__global__ void k_deg_init() {
    int i = blockIdx.x * blockDim.x + threadIdx.x;
    if (i < NN) g_deg[i] = 1;                       // self loop
}
__global__ void k_deg_count(const int* __restrict__ dst) {
    int e = blockIdx.x * blockDim.x + threadIdx.x;
    if (e < NE) atomicAdd(&g_deg[dst[e]], 1);
}
__global__ void k_dis() {
    int i = blockIdx.x * blockDim.x + threadIdx.x;
    if (i < NN) g_dis[i] = rsqrtf((float)g_deg[i]);
}

// ---------------- weight prep: transpose + bf16 hi/lo split ------------------
__global__ void k_prep_w(const float* __restrict__ W1, const float* __restrict__ W2,
                         const float* __restrict__ W3) {
    int i = blockIdx.x * blockDim.x + threadIdx.x;
    if (i < 16384) {
        int k = i >> 7, n = i & 127;
        float v = W1[i];
        __nv_bfloat16 hi = __float2bfloat16_rn(v);
        g_w1h[n * 128 + k] = hi;
        g_w1l[n * 128 + k] = __float2bfloat16_rn(v - __bfloat162float(hi));
        v = W2[i]; hi = __float2bfloat16_rn(v);
        g_w2h[n * 128 + k] = hi;
        g_w2l[n * 128 + k] = __float2bfloat16_rn(v - __bfloat162float(hi));
    }
    if (i < 8192) {
        int k = i >> 6, n = i & 63;
        float v = W3[i];
        __nv_bfloat16 hi = __float2bfloat16_rn(v);
        g_w3h[n * 128 + k] = hi;
        g_w3l[n * 128 + k] = __float2bfloat16_rn(v - __bfloat162float(hi));
    }
}

// ---------------- CSR build --------------------------------------------------
__global__ void k_scan1() {
    __shared__ int s[256];
    int t = threadIdx.x;
    int i = blockIdx.x * 256 + t;
    int v = (i < NN) ? (g_deg[i] - 1) : 0;
    s[t] = v; __syncthreads();
#pragma unroll
    for (int off = 1; off < 256; off <<= 1) {
        int a = (t >= off) ? s[t - off] : 0;
        __syncthreads();
        s[t] += a; __syncthreads();
    }
    if (i < NN) g_off[i] = s[t] - v;
    if (t == 255) g_bsum[blockIdx.x] = s[255];
}
__global__ void k_scan2() {
    __shared__ int s[512];
    int t = threadIdx.x;
    int v = (t < NBLK) ? g_bsum[t] : 0;
    s[t] = v; __syncthreads();
#pragma unroll
    for (int off = 1; off < 512; off <<= 1) {
        int a = (t >= off) ? s[t - off] : 0;
        __syncthreads();
        s[t] += a; __syncthreads();
    }
    g_bscan[t] = s[t] - v;
}
__global__ void k_scan3() {
    int i = blockIdx.x * blockDim.x + threadIdx.x;
    if (i < NN) {
        int o = g_off[i] + g_bscan[i >> 8];
        g_off[i] = o;
        g_cur[i] = o;
    }
    if (i == 0) g_off[NN] = NE;
}
__global__ void k_fill(const int* __restrict__ src, const int* __restrict__ dst) {
    int e = blockIdx.x * blockDim.x + threadIdx.x;
    if (e >= NE) return;
    int pos = atomicAdd(&g_cur[dst[e]], 1);
    g_ep[pos] = src[e];
}

// ---------------- bf16-split tensor-core GEMM: h' = dis * (f(in) @ W) --------
// D = Ah*Bh + Al*Bh + Ah*Bl (fp32 accum). 128-row tiles, K chunked by 64.
// smem rows padded to 72 bf16 (144 B): 144/4 = 36 == 4 mod 32 -> ldmatrix
// conflict-free. 8 warps = 4(M) x 2(N).
template <int COUT, bool RELU_IN>
__global__ void __launch_bounds__(256)
k_gemm_mma(const float* __restrict__ in, const __nv_bfloat16* __restrict__ wh,
           const __nv_bfloat16* __restrict__ wl, const float* __restrict__ bin,
           float* __restrict__ h)
{
    constexpr int PITCH = 144;                 // bytes per smem row (72 bf16)
    constexpr int ASZ = 128 * PITCH;           // 18432
    constexpr int BSZ = COUT * PITCH;
    constexpr int NTW = COUT / 16;             // n8 tiles per warp (8 or 4)

    extern __shared__ char smem[];
    char* Ah = smem;
    char* Al = smem + ASZ;
    char* Bh = smem + 2 * ASZ;
    char* Bl = Bh + BSZ;
    uint32_t sb = smem_u32(smem);

    int tid = threadIdx.x;
    int wid = tid >> 5, lane = tid & 31;
    int wm = wid >> 1, wn = wid & 1;
    int row0 = blockIdx.x * 128;

    float acc[2][NTW][4];
#pragma unroll
    for (int f = 0; f < 2; f++)
#pragma unroll
        for (int t = 0; t < NTW; t++)
#pragma unroll
            for (int q = 0; q < 4; q++) acc[f][t][q] = 0.f;

    // per-lane ldmatrix address components
    uint32_t lrow = lane & 7, quad = lane >> 3;
    uint32_t aoff = sb + (uint32_t)(2 * ASZ * 0) +
                    (wm * 32 + lrow + ((quad & 1) << 3)) * PITCH + ((quad & 2) << 3);
    uint32_t boff = sb + (uint32_t)(2 * ASZ) +
                    (wn * (COUT / 2) + lrow + ((quad & 2) << 2)) * PITCH + ((quad & 1) << 4);

    for (int c = 0; c < 2; c++) {
        // ---- stage A chunk [128 x 64] fp32 -> bf16 hi/lo -------------------
        {
            int r = tid >> 1, half = tid & 1;
            int gr = row0 + r;
            const float* ip = in + (size_t)gr * CIN + c * 64 + half * 32;
            __nv_bfloat162* arh = reinterpret_cast<__nv_bfloat162*>(Ah + r * PITCH + half * 64);
            __nv_bfloat162* arl = reinterpret_cast<__nv_bfloat162*>(Al + r * PITCH + half * 64);
#pragma unroll
            for (int q = 0; q < 8; q++) {
                float4 v = make_float4(0.f, 0.f, 0.f, 0.f);
                if (gr < NN) v = *reinterpret_cast<const float4*>(ip + q * 4);
                if (RELU_IN) {
                    float4 b = *reinterpret_cast<const float4*>(bin + c * 64 + half * 32 + q * 4);
                    v.x = fmaxf(v.x + b.x, 0.f); v.y = fmaxf(v.y + b.y, 0.f);
                    v.z = fmaxf(v.z + b.z, 0.f); v.w = fmaxf(v.w + b.w, 0.f);
                }
                __nv_bfloat162 h0, h1, l0, l1;
                h0.x = __float2bfloat16_rn(v.x); h0.y = __float2bfloat16_rn(v.y);
                h1.x = __float2bfloat16_rn(v.z); h1.y = __float2bfloat16_rn(v.w);
                l0.x = __float2bfloat16_rn(v.x - __bfloat162float(h0.x));
                l0.y = __float2bfloat16_rn(v.y - __bfloat162float(h0.y));
                l1.x = __float2bfloat16_rn(v.z - __bfloat162float(h1.x));
                l1.y = __float2bfloat16_rn(v.w - __bfloat162float(h1.y));
                arh[q * 2] = h0; arh[q * 2 + 1] = h1;
                arl[q * 2] = l0; arl[q * 2 + 1] = l1;
            }
        }
        // ---- stage B chunk [COUT x 64] bf16 copy ---------------------------
        {
            constexpr int TPR = 256 / COUT;    // 2 or 4
            constexpr int VPT = 8 / TPR;       // uint4 per thread: 4 or 2
            int n = tid / TPR, part = tid % TPR;
            const uint4* sh = reinterpret_cast<const uint4*>(wh + n * 128 + c * 64) + part * VPT;
            const uint4* sl = reinterpret_cast<const uint4*>(wl + n * 128 + c * 64) + part * VPT;
            uint4* dh = reinterpret_cast<uint4*>(Bh + n * PITCH) + part * VPT;
            uint4* dl = reinterpret_cast<uint4*>(Bl + n * PITCH) + part * VPT;
#pragma unroll
            for (int v = 0; v < VPT; v++) { dh[v] = sh[v]; dl[v] = sl[v]; }
        }
        __syncthreads();

        // ---- compute: 4 k16 steps ------------------------------------------
#pragma unroll
        for (int kk = 0; kk < 4; kk++) {
            uint32_t ka = (uint32_t)(kk << 5);
            uint32_t afr[2][4], afl[2][4];
            ldsm4(afr[0], aoff + ka);
            ldsm4(afr[1], aoff + 16 * PITCH + ka);
            ldsm4(afl[0], aoff + ASZ + ka);
            ldsm4(afl[1], aoff + ASZ + 16 * PITCH + ka);
#pragma unroll
            for (int tp = 0; tp < NTW / 2; tp++) {
                uint32_t bfr[4], bfl[4];
                ldsm4(bfr, boff + tp * 16 * PITCH + ka);
                ldsm4(bfl, boff + BSZ + tp * 16 * PITCH + ka);
#pragma unroll
                for (int f = 0; f < 2; f++) {
                    mma16816(acc[f][2 * tp],     afr[f], bfr[0], bfr[1]);
                    mma16816(acc[f][2 * tp],     afl[f], bfr[0], bfr[1]);
                    mma16816(acc[f][2 * tp],     afr[f], bfl[0], bfl[1]);
                    mma16816(acc[f][2 * tp + 1], afr[f], bfr[2], bfr[3]);
                    mma16816(acc[f][2 * tp + 1], afl[f], bfr[2], bfr[3]);
                    mma16816(acc[f][2 * tp + 1], afr[f], bfl[2], bfl[3]);
                }
            }
        }
        __syncthreads();
    }

    // ---- epilogue: scale by dis, store h' -----------------------------------
#pragma unroll
    for (int f = 0; f < 2; f++) {
        int r0g = row0 + wm * 32 + f * 16 + (lane >> 2);
        float ds0 = (r0g < NN) ? g_dis[r0g] : 0.f;
        float ds1 = (r0g + 8 < NN) ? g_dis[r0g + 8] : 0.f;
#pragma unroll
        for (int t = 0; t < NTW; t++) {
            int ncol = wn * (COUT / 2) + t * 8 + ((lane & 3) << 1);
            if (r0g < NN) {
                float2 o = make_float2(acc[f][t][0] * ds0, acc[f][t][1] * ds0);
                *reinterpret_cast<float2*>(h + (size_t)r0g * COUT + ncol) = o;
            }
            if (r0g + 8 < NN) {
                float2 o = make_float2(acc[f][t][2] * ds1, acc[f][t][3] * ds1);
                *reinterpret_cast<float2*>(h + (size_t)(r0g + 8) * COUT + ncol) = o;
            }
        }
    }
}

// ---------------- gather: agg[d] = dis[d]*(sum_src h'[src] + h'[d]) ----------
__global__ void k_gather128(const float* __restrict__ h, float* __restrict__ agg)
{
    int warp = (blockIdx.x * blockDim.x + threadIdx.x) >> 5;
    int lane = threadIdx.x & 31;
    if (warp >= NN) return;
    int beg = g_off[warp], end = g_off[warp + 1];
    const float4* hp = reinterpret_cast<const float4*>(h);
    float4 acc = hp[warp * 32 + lane];                 // self term
    int i = beg;
    for (; i + 4 <= end; i += 4) {
        int s0 = g_ep[i], s1 = g_ep[i + 1], s2 = g_ep[i + 2], s3 = g_ep[i + 3];
        float4 v0 = hp[s0 * 32 + lane];
        float4 v1 = hp[s1 * 32 + lane];
        float4 v2 = hp[s2 * 32 + lane];
        float4 v3 = hp[s3 * 32 + lane];
        acc.x += (v0.x + v1.x) + (v2.x + v3.x);
        acc.y += (v0.y + v1.y) + (v2.y + v3.y);
        acc.z += (v0.z + v1.z) + (v2.z + v3.z);
        acc.w += (v0.w + v1.w) + (v2.w + v3.w);
    }
    for (; i < end; i++) {
        float4 v = hp[g_ep[i] * 32 + lane];
        acc.x += v.x; acc.y += v.y; acc.z += v.z; acc.w += v.w;
    }
    float dd = g_dis[warp];
    acc.x *= dd; acc.y *= dd; acc.z *= dd; acc.w *= dd;
    reinterpret_cast<float4*>(agg)[warp * 32 + lane] = acc;
}

__global__ void k_gather64f(const float* __restrict__ h, const float* __restrict__ b3,
                            float* __restrict__ out)
{
    int warp = (blockIdx.x * blockDim.x + threadIdx.x) >> 5;
    int lane = threadIdx.x & 31;
    if (warp >= NN) return;
    int beg = g_off[warp], end = g_off[warp + 1];
    const float2* hp = reinterpret_cast<const float2*>(h);
    float2 acc = hp[warp * 32 + lane];                 // self term
    int i = beg;
    for (; i + 4 <= end; i += 4) {
        int s0 = g_ep[i], s1 = g_ep[i + 1], s2 = g_ep[i + 2], s3 = g_ep[i + 3];
        float2 v0 = hp[s0 * 32 + lane];
        float2 v1 = hp[s1 * 32 + lane];
        float2 v2 = hp[s2 * 32 + lane];
        float2 v3 = hp[s3 * 32 + lane];
        acc.x += (v0.x + v1.x) + (v2.x + v3.x);
        acc.y += (v0.y + v1.y) + (v2.y + v3.y);
    }
    for (; i < end; i++) {
        float2 v = hp[g_ep[i] * 32 + lane];
        acc.x += v.x; acc.y += v.y;
    }
    float dd = g_dis[warp];
    float2 b = reinterpret_cast<const float2*>(b3)[lane];
    float2 r;
    r.x = fmaf(acc.x, dd, b.x);
    r.y = fmaf(acc.y, dd, b.y);
    reinterpret_cast<float2*>(out)[warp * 32 + lane] = r;
}

// ---------------- launcher ---------------------------------------------------
extern "C" void kernel_launch(void* const* d_in, const int* in_sizes, int n_in,
                              void* d_out, int out_size)
{
    const float* x  = (const float*)d_in[0];
    const int*   ei = (const int*)d_in[1];
    const float* W1 = (const float*)d_in[2];
    const float* b1 = (const float*)d_in[3];
    const float* W2 = (const float*)d_in[4];
    const float* b2 = (const float*)d_in[5];
    const float* W3 = (const float*)d_in[6];
    const float* b3 = (const float*)d_in[7];
    float* out = (float*)d_out;

    const int* src = ei;            // edge_index[0]
    const int* dst = ei + NE;       // edge_index[1]

    float *ph = nullptr, *pa = nullptr;
    cudaGetSymbolAddress((void**)&ph, g_h);
    cudaGetSymbolAddress((void**)&pa, g_a);
    __nv_bfloat16 *w1h, *w1l, *w2h, *w2l, *w3h, *w3l;
    cudaGetSymbolAddress((void**)&w1h, g_w1h);
    cudaGetSymbolAddress((void**)&w1l, g_w1l);
    cudaGetSymbolAddress((void**)&w2h, g_w2h);
    cudaGetSymbolAddress((void**)&w2l, g_w2l);
    cudaGetSymbolAddress((void**)&w3h, g_w3h);
    cudaGetSymbolAddress((void**)&w3l, g_w3l);

    const int smem128 = 2 * 128 * 144 + 2 * 128 * 144;   // 73728
    const int smem64  = 2 * 128 * 144 + 2 * 64 * 144;    // 55296
    cudaFuncSetAttribute(k_gemm_mma<128, false>, cudaFuncAttributeMaxDynamicSharedMemorySize, smem128);
    cudaFuncSetAttribute(k_gemm_mma<128, true>,  cudaFuncAttributeMaxDynamicSharedMemorySize, smem128);
    cudaFuncSetAttribute(k_gemm_mma<64,  true>,  cudaFuncAttributeMaxDynamicSharedMemorySize, smem64);

    // normalization + CSR build + weight prep
    k_deg_init<<<(NN + 255) / 256, 256>>>();
    k_deg_count<<<(NE + 255) / 256, 256>>>(dst);
    k_dis<<<(NN + 255) / 256, 256>>>();
    k_prep_w<<<64, 256>>>(W1, W2, W3);
    k_scan1<<<NBLK, 256>>>();
    k_scan2<<<1, 512>>>();
    k_scan3<<<NBLK, 256>>>();
    k_fill<<<(NE + 255) / 256, 256>>>(src, dst);

    const int gB = (NN + 127) / 128;         // 782 M-tiles
    const int gG = (NN * 32 + 255) / 256;    // warp per node

    // layer 1
    k_gemm_mma<128, false><<<gB, 256, smem128>>>(x, w1h, w1l, b1, ph);
    k_gather128<<<gG, 256>>>(ph, pa);
    // layer 2
    k_gemm_mma<128, true><<<gB, 256, smem128>>>(pa, w2h, w2l, b1, ph);
    k_gather128<<<gG, 256>>>(ph, pa);
    // layer 3 (COUT=64) + fused final bias
    k_gemm_mma<64, true><<<gB, 256, smem64>>>(pa, w3h, w3l, b2, ph);
    k_gather64f<<<gG, 256>>>(ph, b3, out);
}